// round 9
// baseline (speedup 1.0000x reference)
#include <cuda_runtime.h>
#include <cstdint>
#include <cstddef>

// RWW whole-brain sim, 8-CTA cluster, Con_Mtx register-resident.
// R9 = R8 compute structure, exchange replaced:
//   - data: 64 epilogue threads each ship 2x st.shared::cluster.v4 to a
//     fixed destination (128x16B received per CTA) -- no bulk-copy engine
//   - signal: per-(buffer,source) flag words, st.release.cluster with the
//     monotonic step value; ZERO barrier RMWs
//   - consumers poll 8 local flags (2x ld.volatile.v4 + compare) then
//     fence.acq_rel.cluster (relaxed-poll + acquire-fence pattern)

#define NREG    512
#define NSTEPS  20000
#define NCTAS   8
#define NTHR    512

#define EF 68                          // x stripe stride in floats (272 B)
#define PF 544                         // floats per x parity buffer
#define SUM_OFF  4352                  // 512 partial sums (2048 B)
#define STG_OFF  6400                  // 2 x 256 B staging
#define FLG_OFF  6912                  // flags[2][8] u32 (64 B)
#define SMEM_BYTES 7168

__device__ __forceinline__ unsigned long long ffma2(
    unsigned long long a, unsigned long long b, unsigned long long c) {
    unsigned long long d;
    asm("fma.rn.f32x2 %0, %1, %2, %3;" : "=l"(d) : "l"(a), "l"(b), "l"(c));
    return d;
}
__device__ __forceinline__ float fsum2(unsigned long long a) {
    float2 f = *reinterpret_cast<float2*>(&a);
    return f.x + f.y;
}

__device__ __forceinline__ float Hfun(float I, float a, float b, float d, float bigc) {
    float x     = fmaf(a, I, -b);
    float numer = fabsf(x) + 1e-9f;
    float neg   = -d * x;
    float e     = __expf(fminf(neg, 51.0f));
    float den_s = fabsf(1.0f - e) + 1e-9f * d;
    float den_b = fabsf(1.0f - bigc * neg) + 1e-9f * d;
    float denom = (neg > 50.0f) ? den_b : den_s;
    return __fdividef(numer, denom);
}

extern __shared__ float smx[];

__global__ void __launch_bounds__(NTHR, 1) __cluster_dims__(NCTAS, 1, 1)
rww_kernel(const float* __restrict__ init_state,   // (512, 2)
           const float* __restrict__ Con,          // (512, 512) row-major
           const float* __restrict__ vofT,         // (20000, 512)
           float* __restrict__ out)                // 1024 final + 20000*1024 hist
{
    const int tid  = (int)threadIdx.x;
    const int cta  = (int)blockIdx.x;          // cluster rank
    const int r    = tid >> 3;                 // local row 0..63
    const int q    = tid & 7;                  // column eighth 0..7
    const int j    = cta * 64 + r;             // global region of this row

    uint32_t sb;
    asm("{ .reg .u64 t; cvta.to.shared.u64 t, %1; cvt.u32.u64 %0, t; }"
        : "=r"(sb) : "l"(smx));

    // ---- flags[2][8] = 0 ----
    if (tid < 16)
        ((uint32_t*)((char*)smx + FLG_OFF))[tid] = 0u;

    // ---- Con row segment: cols q*64..q*64+63 -> 32 packed f32x2 regs ----
    unsigned long long c64[32];
    {
        const ulonglong2* src =
            (const ulonglong2*)(Con + (size_t)j * NREG + (size_t)q * 64);
        #pragma unroll
        for (int it = 0; it < 16; ++it) {
            ulonglong2 t2 = src[it];
            c64[2*it] = t2.x; c64[2*it+1] = t2.y;
        }
    }

    // ---- init x buffer 0 locally: x[k] @ (k>>6)*EF + (k&63) ----
    if (tid < NREG)
        smx[(tid >> 6) * EF + (tid & 63)] = init_state[2 * tid];

    // ---- per-region state on threads 0..63 only ----
    float sE = 0.0f, sI = 0.0f;
    if (tid < 64) {
        sE = init_state[2 * (cta * 64 + tid)];
        sI = init_state[2 * (cta * 64 + tid) + 1];
    }

    // ---- hoisted per-thread remote addresses (fixed destination) ----
    // data: thread k<64 sends chunk pair cp=(k&7)*2 of this CTA's stripe
    //       to destination dest=k>>3, both parities.
    // flag: threads 0..7 write flags[b^1][cta] at dest=tid.
    uint32_t rX0 = 0, rX1 = 0, rF0 = 0, rF1 = 0;
    if (tid < 64) {
        const int dest = tid >> 3;
        const int cp   = (tid & 7) * 2;
        uint32_t a0 = sb + (uint32_t)(cta * (EF * 4) + cp * 16);
        asm("mapa.shared::cluster.u32 %0, %1, %2;" : "=r"(rX0) : "r"(a0), "r"(dest));
        asm("mapa.shared::cluster.u32 %0, %1, %2;"
            : "=r"(rX1) : "r"(a0 + (uint32_t)(PF * 4)), "r"(dest));
        if (tid < 8) {
            uint32_t f0 = sb + (uint32_t)(FLG_OFF + cta * 4);
            asm("mapa.shared::cluster.u32 %0, %1, %2;" : "=r"(rF0) : "r"(f0), "r"(tid));
            asm("mapa.shared::cluster.u32 %0, %1, %2;" : "=r"(rF1) : "r"(f0 + 32u), "r"(tid));
        }
    }

    __syncthreads();
    asm volatile("barrier.cluster.arrive.aligned;" ::: "memory");
    asm volatile("barrier.cluster.wait.aligned;"   ::: "memory");

    // noise pipeline (threads 0..63 only), 2 deep
    float vc = 0.0f, vn = 0.0f;
    if (tid < 64) {
        vc = __ldg(vofT + cta * 64 + tid);
        vn = __ldg(vofT + NREG + cta * 64 + tid);
    }
    float2* outv = (float2*)out;

    for (int t = 0; t < NSTEPS; ++t) {
        const int b = t & 1;

        // ---- wait: poll the 8 local flags for value t (skip t=0) ----
        if (t) {
            const uint32_t fa = sb + (uint32_t)(FLG_OFF + b * 32);
            const uint32_t tt = (uint32_t)t;
            asm volatile(
                "{\n\t"
                ".reg .u32 a0,a1,a2,a3,a4,a5,a6,a7,x;\n\t"
                ".reg .pred P;\n"
                "PL_%=:\n\t"
                "ld.volatile.shared.v4.u32 {a0,a1,a2,a3}, [%0];\n\t"
                "ld.volatile.shared.v4.u32 {a4,a5,a6,a7}, [%0+16];\n\t"
                "xor.b32 a0,a0,%1; xor.b32 a1,a1,%1;\n\t"
                "xor.b32 a2,a2,%1; xor.b32 a3,a3,%1;\n\t"
                "xor.b32 a4,a4,%1; xor.b32 a5,a5,%1;\n\t"
                "xor.b32 a6,a6,%1; xor.b32 a7,a7,%1;\n\t"
                "or.b32 a0,a0,a1; or.b32 a2,a2,a3;\n\t"
                "or.b32 a4,a4,a5; or.b32 a6,a6,a7;\n\t"
                "or.b32 a0,a0,a2; or.b32 a4,a4,a6;\n\t"
                "or.b32 x,a0,a4;\n\t"
                "setp.ne.u32 P, x, 0;\n\t"
                "@P bra PL_%=;\n\t"
                "}"
                :: "r"(fa), "r"(tt) : "memory");
            asm volatile("fence.acq_rel.cluster;" ::: "memory");
        }

        // ---- matvec: 64 cols/thread -> one partial sum, STS to smem ----
        const ulonglong2* x2 = (const ulonglong2*)
            ((const char*)smx + (b ? PF * 4 : 0) + q * (EF * 4));
        unsigned long long a0 = 0ULL, a1 = 0ULL, a2 = 0ULL, a3 = 0ULL;
        #pragma unroll
        for (int it = 0; it < 8; ++it) {
            ulonglong2 xa = x2[2*it];
            ulonglong2 xb = x2[2*it+1];
            a0 = ffma2(c64[4*it+0], xa.x, a0);
            a1 = ffma2(c64[4*it+1], xa.y, a1);
            a2 = ffma2(c64[4*it+2], xb.x, a2);
            a3 = ffma2(c64[4*it+3], xb.y, a3);
        }
        smx[SUM_OFF / 4 + tid] =
            (fsum2(a0) + fsum2(a1)) + (fsum2(a2) + fsum2(a3));

        __syncthreads();   // partials visible; warps 2-15 sprint to next poll

        if (tid < 64) {
            // ---- reduce 8 partials for my row ----
            const float4* sp = (const float4*)(smx + SUM_OFF / 4 + tid * 8);
            float4 s0 = sp[0], s1 = sp[1];
            float acc = ((s0.x + s0.y) + (s0.z + s0.w))
                      + ((s1.x + s1.y) + (s1.z + s1.w));

            // ---- epilogue (one thread per row) ----
            float I_E = 0.382f  + 0.21f * sE + 3.0f * acc - sI;  // LAMBDA=0
            float I_I = 0.2674f + 0.15f * sE - sI;
            float rE = Hfun(I_E, 310.0f, 125.0f, 0.16f,  1e9f);
            float rI = Hfun(I_I, 615.0f, 177.0f, 0.087f, 1e5f);
            float dE = -sE * 0.01f + (1.0f - sE) * 6.41e-4f * rE + 0.01f * vc;
            float dI = -sI * 0.1f  + 1.0e-3f * rI + 0.01f * vc;
            sE = fmaf(1e-4f, dE, sE);
            sI = fmaf(1e-4f, dI, sI);

            // stage new S_E + history
            smx[STG_OFF / 4 + b * 64 + tid] = sE;
            outv[512 + (size_t)t * NREG + cta * 64 + tid] = make_float2(sE, sI);

            asm volatile("bar.sync 1, 64;" ::: "memory");  // staging complete

            if (t + 1 < NSTEPS) {   // uniform guard across the 64 threads
                // ---- data: 2x 16B remote stores to my fixed destination ----
                const int cp = (tid & 7) * 2;
                const float4* stg4 = (const float4*)(smx + STG_OFF / 4 + b * 64);
                float4 d0 = stg4[cp], d1 = stg4[cp + 1];
                uint32_t base = b ? rX0 : rX1;       // dest buffer b^1
                asm volatile("st.shared::cluster.v4.f32 [%0], {%1,%2,%3,%4};"
                             :: "r"(base), "f"(d0.x), "f"(d0.y), "f"(d0.z), "f"(d0.w)
                             : "memory");
                asm volatile("st.shared::cluster.v4.f32 [%0], {%1,%2,%3,%4};"
                             :: "r"(base + 16u), "f"(d1.x), "f"(d1.y), "f"(d1.z), "f"(d1.w)
                             : "memory");

                asm volatile("bar.sync 1, 64;" ::: "memory");  // all stores issued

                // ---- signal: release-store flags[b^1][cta] = t+1 ----
                if (tid < 8) {
                    uint32_t fdst = b ? rF0 : rF1;
                    asm volatile("st.release.cluster.shared::cluster.u32 [%0], %1;"
                                 :: "r"(fdst), "r"((uint32_t)(t + 1)) : "memory");
                }
            }

            vc = vn;
            int t2 = t + 2; if (t2 >= NSTEPS) t2 = NSTEPS - 1;
            vn = __ldg(vofT + (size_t)t2 * NREG + cta * 64 + tid);
        }
    }

    if (tid < 64) outv[cta * 64 + tid] = make_float2(sE, sI);

    // drain: nobody exits while peers may still write our smem
    asm volatile("barrier.cluster.arrive.aligned;" ::: "memory");
    asm volatile("barrier.cluster.wait.aligned;"   ::: "memory");
}

extern "C" void kernel_launch(void* const* d_in, const int* in_sizes, int n_in,
                              void* d_out, int out_size) {
    const float* init = nullptr;
    const float* con  = nullptr;
    const float* v    = nullptr;
    for (int i = 0; i < n_in; ++i) {
        if      (in_sizes[i] == NREG * 2)      init = (const float*)d_in[i];
        else if (in_sizes[i] == NREG * NREG)   con  = (const float*)d_in[i];
        else if (in_sizes[i] == NSTEPS * NREG) v    = (const float*)d_in[i];
    }
    rww_kernel<<<NCTAS, NTHR, SMEM_BYTES>>>(init, con, v, (float*)d_out);
    (void)out_size;
}

// round 10
// speedup vs baseline: 1.0810x; 1.0810x over previous
#include <cuda_runtime.h>
#include <cstdint>
#include <cstddef>

// RWW whole-brain sim, 8-CTA cluster, Con_Mtx register-resident.
// R10: direct-store exchange + count-8 mbarrier signaling.
//   - warp-autonomous: shfl reduce + replicated epilogue, each warp packs
//     its 4 new S_E into a float4 and lanes 0-7 ship it via
//     st.shared::cluster.v4 to dest=lane (128x16B received per CTA)
//   - __syncthreads, then threads 0-7 send ONE mbarrier.arrive.release
//     each to their destination (8 RMWs/dest/step; R4's 128 was the bug)
//   - receivers sleep in mbarrier.try_wait (R9 lesson: never soft-poll smem)

#define NREG    512
#define NSTEPS  20000
#define NCTAS   8
#define NTHR    512

#define EF 68                          // x stripe stride in floats (272 B)
#define PF 544                         // floats per x parity buffer
#define XB      (2 * PF * 4)           // 4352 B x buffers
#define MB_OFF  4608                   // 2 mbarriers
#define SMEM_BYTES 4736

__device__ __forceinline__ unsigned long long ffma2(
    unsigned long long a, unsigned long long b, unsigned long long c) {
    unsigned long long d;
    asm("fma.rn.f32x2 %0, %1, %2, %3;" : "=l"(d) : "l"(a), "l"(b), "l"(c));
    return d;
}
__device__ __forceinline__ float fsum2(unsigned long long a) {
    float2 f = *reinterpret_cast<float2*>(&a);
    return f.x + f.y;
}
__device__ __forceinline__ void mbar_wait(uint32_t mb, uint32_t par) {
    asm volatile(
        "{\n\t"
        ".reg .pred P;\n"
        "WL_%=:\n\t"
        "mbarrier.try_wait.parity.acquire.cluster.shared::cta.b64 P, [%0], %1, 0x989680;\n\t"
        "@!P bra WL_%=;\n\t"
        "}" :: "r"(mb), "r"(par) : "memory");
}

__device__ __forceinline__ float Hfun(float I, float a, float b, float d, float bigc) {
    float x     = fmaf(a, I, -b);
    float numer = fabsf(x) + 1e-9f;
    float neg   = -d * x;
    float e     = __expf(fminf(neg, 51.0f));
    float den_s = fabsf(1.0f - e) + 1e-9f * d;
    float den_b = fabsf(1.0f - bigc * neg) + 1e-9f * d;
    float denom = (neg > 50.0f) ? den_b : den_s;
    return __fdividef(numer, denom);
}

extern __shared__ float smx[];

__global__ void __launch_bounds__(NTHR, 1) __cluster_dims__(NCTAS, 1, 1)
rww_kernel(const float* __restrict__ init_state,   // (512, 2)
           const float* __restrict__ Con,          // (512, 512) row-major
           const float* __restrict__ vofT,         // (20000, 512)
           float* __restrict__ out)                // 1024 final + 20000*1024 hist
{
    const int tid  = (int)threadIdx.x;
    const int cta  = (int)blockIdx.x;          // cluster rank
    const int lane = tid & 31;
    const int wrp  = tid >> 5;                 // warp 0..15 (rows 4w..4w+3)
    const int r    = tid >> 3;                 // local row 0..63
    const int q    = tid & 7;                  // column eighth 0..7
    const int j    = cta * 64 + r;             // global region of this row

    uint32_t sb;
    asm("{ .reg .u64 t; cvta.to.shared.u64 t, %1; cvt.u32.u64 %0, t; }"
        : "=r"(sb) : "l"(smx));
    const uint32_t mb0 = sb + MB_OFF;
    const uint32_t mb1 = sb + MB_OFF + 8;

    // 2 mbarriers, count = 8 (one arrive per source CTA); auto phase reset
    if (tid == 0) {
        asm volatile("mbarrier.init.shared.b64 [%0], %1;" :: "r"(mb0), "r"(8));
        asm volatile("mbarrier.init.shared.b64 [%0], %1;" :: "r"(mb1), "r"(8));
    }

    // ---- Con row segment: cols q*64..q*64+63 -> 32 packed f32x2 regs ----
    unsigned long long c64[32];
    {
        const ulonglong2* src =
            (const ulonglong2*)(Con + (size_t)j * NREG + (size_t)q * 64);
        #pragma unroll
        for (int it = 0; it < 16; ++it) {
            ulonglong2 t2 = src[it];
            c64[2*it] = t2.x; c64[2*it+1] = t2.y;
        }
    }

    // ---- init x buffer 0 locally: x[k] @ (k>>6)*EF + (k&63) ----
    if (tid < NREG)
        smx[(tid >> 6) * EF + (tid & 63)] = init_state[2 * tid];

    // ---- per-region state replicated on the 8 lanes of each row ----
    float sE = init_state[2 * j];
    float sI = init_state[2 * j + 1];

    // ---- hoisted remote addresses ----
    // data: lanes 0..7 of warp w store the warp's float4 (rows 4w..4w+3)
    //       into dest=lane's x stripe at (cta*EF + 4*wrp)*4, both parities.
    uint32_t rX0 = 0, rX1 = 0;
    if (lane < 8) {
        uint32_t a0 = sb + (uint32_t)((cta * EF + 4 * wrp) * 4);
        asm("mapa.shared::cluster.u32 %0, %1, %2;" : "=r"(rX0) : "r"(a0), "r"(lane));
        asm("mapa.shared::cluster.u32 %0, %1, %2;"
            : "=r"(rX1) : "r"(a0 + (uint32_t)(PF * 4)), "r"(lane));
    }
    // signal: threads 0..7 arrive at dest=tid's mbarrier, both parities
    uint32_t rA0 = 0, rA1 = 0;
    if (tid < 8) {
        asm("mapa.shared::cluster.u32 %0, %1, %2;" : "=r"(rA0) : "r"(mb0), "r"(tid));
        asm("mapa.shared::cluster.u32 %0, %1, %2;" : "=r"(rA1) : "r"(mb1), "r"(tid));
    }

    __syncthreads();
    asm volatile("barrier.cluster.arrive.aligned;" ::: "memory");
    asm volatile("barrier.cluster.wait.aligned;"   ::: "memory");

    // noise pipeline, 2 deep (8 lanes per row share the address)
    float vc = __ldg(vofT + j);
    float vn = __ldg(vofT + NREG + j);
    float2* outv = (float2*)out;

    int ph0 = 0, ph1 = 0;

    for (int t = 0; t < NSTEPS; ++t) {
        const int b = t & 1;

        // ---- wait for this step's x data (skip t=0: local init) ----
        if (t) {
            if (b) { mbar_wait(mb1, (uint32_t)ph1); ph1 ^= 1; }
            else   { mbar_wait(mb0, (uint32_t)ph0); ph0 ^= 1; }
        }

        // ---- matvec: 64 cols/thread, Con in regs, x from smem (f32x2) ----
        const ulonglong2* x2 = (const ulonglong2*)
            ((const char*)smx + (b ? PF * 4 : 0) + q * (EF * 4));
        unsigned long long a0 = 0ULL, a1 = 0ULL, a2 = 0ULL, a3 = 0ULL;
        #pragma unroll
        for (int it = 0; it < 8; ++it) {
            ulonglong2 xa = x2[2*it];
            ulonglong2 xb = x2[2*it+1];
            a0 = ffma2(c64[4*it+0], xa.x, a0);
            a1 = ffma2(c64[4*it+1], xa.y, a1);
            a2 = ffma2(c64[4*it+2], xb.x, a2);
            a3 = ffma2(c64[4*it+3], xb.y, a3);
        }
        float acc = (fsum2(a0) + fsum2(a1)) + (fsum2(a2) + fsum2(a3));
        acc += __shfl_xor_sync(0xffffffffu, acc, 1);
        acc += __shfl_xor_sync(0xffffffffu, acc, 2);
        acc += __shfl_xor_sync(0xffffffffu, acc, 4);
        // all 8 lanes of each row hold the full dot product

        // ---- epilogue (replicated, bit-identical across the 8 lanes) ----
        float I_E = 0.382f  + 0.21f * sE + 3.0f * acc - sI;   // LAMBDA=0 folded
        float I_I = 0.2674f + 0.15f * sE - sI;
        float rE = Hfun(I_E, 310.0f, 125.0f, 0.16f,  1e9f);
        float rI = Hfun(I_I, 615.0f, 177.0f, 0.087f, 1e5f);
        float dE = -sE * 0.01f + (1.0f - sE) * 6.41e-4f * rE + 0.01f * vc;
        float dI = -sI * 0.1f  + 1.0e-3f * rI + 0.01f * vc;
        sE = fmaf(1e-4f, dE, sE);
        sI = fmaf(1e-4f, dI, sI);

        // ---- pack warp's 4 rows (lead lanes 0,8,16,24) into a float4 ----
        float4 sv;
        sv.x = __shfl_sync(0xffffffffu, sE, 0);
        sv.y = __shfl_sync(0xffffffffu, sE, 8);
        sv.z = __shfl_sync(0xffffffffu, sE, 16);
        sv.w = __shfl_sync(0xffffffffu, sE, 24);

        // ---- per-warp direct remote stores to buffer b^1 of all 8 CTAs ----
        if (lane < 8 && (t + 1 < NSTEPS)) {
            uint32_t rx = b ? rX0 : rX1;
            asm volatile("st.shared::cluster.v4.f32 [%0], {%1,%2,%3,%4};"
                         :: "r"(rx), "f"(sv.x), "f"(sv.y), "f"(sv.z), "f"(sv.w)
                         : "memory");
        }

        // history (off critical path) + next noise
        if (q == 0)
            outv[512 + (size_t)t * NREG + j] = make_float2(sE, sI);
        int t2 = t + 2; if (t2 >= NSTEPS) t2 = NSTEPS - 1;
        float vf = __ldg(vofT + (size_t)t2 * NREG + j);

        // order all warps' remote stores, then one release-arrive per dest
        __syncthreads();
        if (tid < 8 && (t + 1 < NSTEPS)) {
            uint32_t ra = b ? rA0 : rA1;   // dest's mbar[b^1]
            asm volatile("mbarrier.arrive.release.cluster.shared::cluster.b64 _, [%0];"
                         :: "r"(ra) : "memory");
        }

        vc = vn; vn = vf;
    }

    if (q == 0) outv[j] = make_float2(sE, sI);

    // drain: nobody exits while peers may still write our smem
    asm volatile("barrier.cluster.arrive.aligned;" ::: "memory");
    asm volatile("barrier.cluster.wait.aligned;"   ::: "memory");
}

extern "C" void kernel_launch(void* const* d_in, const int* in_sizes, int n_in,
                              void* d_out, int out_size) {
    const float* init = nullptr;
    const float* con  = nullptr;
    const float* v    = nullptr;
    for (int i = 0; i < n_in; ++i) {
        if      (in_sizes[i] == NREG * 2)      init = (const float*)d_in[i];
        else if (in_sizes[i] == NREG * NREG)   con  = (const float*)d_in[i];
        else if (in_sizes[i] == NSTEPS * NREG) v    = (const float*)d_in[i];
    }
    rww_kernel<<<NCTAS, NTHR, SMEM_BYTES>>>(init, con, v, (float*)d_out);
    (void)out_size;
}

// round 11
// speedup vs baseline: 1.4784x; 1.3675x over previous
#include <cuda_runtime.h>
#include <cstdint>
#include <cstddef>

// RWW whole-brain sim, 8-CTA cluster, Con_Mtx register-resident.
// R11 = R8 (champion: 8x512 threads, bulk-copy + tx-mbarrier exchange) with:
//   - 7 copies/step (self-stripe read from staging; bank-group preserved
//     via cta*16 staging shift), expect_tx = 1792
//   - paired-thread epilogue: even lane computes H_E, odd computes H_I
//     (branchless constant select), shfl.xor(1) exchange, identical update
//   - history STG + noise LDG after copy issuance

#define NREG    512
#define NSTEPS  20000
#define NCTAS   8
#define NTHR    512

#define EF 68                          // x stripe stride floats (272 B)
#define PF 544                         // floats per x parity buffer
#define PB (PF * 4)                    // 2176 B
#define SUM_OFF  4352                  // 512 partial sums (2048 B)
#define STG_OFF  6400                  // staging: + cta*16 + b*256 (1024 B rsvd)
#define MB_OFF   7424                  // 2 mbarriers
#define SMEM_BYTES 7680

__device__ __forceinline__ unsigned long long ffma2(
    unsigned long long a, unsigned long long b, unsigned long long c) {
    unsigned long long d;
    asm("fma.rn.f32x2 %0, %1, %2, %3;" : "=l"(d) : "l"(a), "l"(b), "l"(c));
    return d;
}
__device__ __forceinline__ float fsum2(unsigned long long a) {
    float2 f = *reinterpret_cast<float2*>(&a);
    return f.x + f.y;
}
__device__ __forceinline__ void mbar_wait(uint32_t mb, uint32_t par) {
    asm volatile(
        "{\n\t"
        ".reg .pred P;\n"
        "WL_%=:\n\t"
        "mbarrier.try_wait.parity.acquire.cluster.shared::cta.b64 P, [%0], %1, 0x989680;\n\t"
        "@!P bra WL_%=;\n\t"
        "}" :: "r"(mb), "r"(par) : "memory");
}

__device__ __forceinline__ float Hfun(float I, float a, float b, float d, float bigc) {
    float x     = fmaf(a, I, -b);
    float numer = fabsf(x) + 1e-9f;
    float neg   = -d * x;
    float e     = __expf(fminf(neg, 51.0f));
    float den_s = fabsf(1.0f - e) + 1e-9f * d;
    float den_b = fabsf(1.0f - bigc * neg) + 1e-9f * d;
    float denom = (neg > 50.0f) ? den_b : den_s;
    return __fdividef(numer, denom);
}

extern __shared__ float smx[];

__global__ void __launch_bounds__(NTHR, 1) __cluster_dims__(NCTAS, 1, 1)
rww_kernel(const float* __restrict__ init_state,   // (512, 2)
           const float* __restrict__ Con,          // (512, 512) row-major
           const float* __restrict__ vofT,         // (20000, 512)
           float* __restrict__ out)                // 1024 final + 20000*1024 hist
{
    const int tid  = (int)threadIdx.x;
    const int cta  = (int)blockIdx.x;          // cluster rank
    const int r    = tid >> 3;                 // local row 0..63
    const int q    = tid & 7;                  // column eighth 0..7
    const int j    = cta * 64 + r;             // global region of this row

    uint32_t sb;
    asm("{ .reg .u64 t; cvta.to.shared.u64 t, %1; cvt.u32.u64 %0, t; }"
        : "=r"(sb) : "l"(smx));
    const uint32_t mb0 = sb + MB_OFF;
    const uint32_t mb1 = sb + MB_OFF + 8;

    if (tid == 0) {
        asm volatile("mbarrier.init.shared.b64 [%0], %1;" :: "r"(mb0), "r"(1));
        asm volatile("mbarrier.init.shared.b64 [%0], %1;" :: "r"(mb1), "r"(1));
        asm volatile("mbarrier.arrive.expect_tx.shared.b64 _, [%0], %1;"
                     :: "r"(mb0), "r"(1792) : "memory");
        asm volatile("mbarrier.arrive.expect_tx.shared.b64 _, [%0], %1;"
                     :: "r"(mb1), "r"(1792) : "memory");
    }

    // ---- Con row segment: cols q*64..q*64+63 -> 32 packed f32x2 regs ----
    unsigned long long c64[32];
    {
        const ulonglong2* src =
            (const ulonglong2*)(Con + (size_t)j * NREG + (size_t)q * 64);
        #pragma unroll
        for (int it = 0; it < 16; ++it) {
            ulonglong2 t2 = src[it];
            c64[2*it] = t2.x; c64[2*it+1] = t2.y;
        }
    }

    // ---- init x buffer 0 locally: x[k] @ (k>>6)*EF + (k&63) ----
    if (tid < NREG)
        smx[(tid >> 6) * EF + (tid & 63)] = init_state[2 * tid];

    // ---- per-row state on threads 0..127 (pair per row, replicated) ----
    const int row  = tid >> 1;                 // valid for tid < 128
    const bool epi = (tid < 128);
    const int par  = tid & 1;                  // 0: E-side, 1: I-side
    float sE = 0.0f, sI = 0.0f;
    if (epi) {
        sE = init_state[2 * (cta * 64 + row)];
        sI = init_state[2 * (cta * 64 + row) + 1];
    }
    // bootstrap staging buffer b'=1 (read at t=0 by q==cta threads)
    if (epi && par == 0)
        smx[(STG_OFF + cta * 16 + 256) / 4 + row] = sE;

    // ---- per-thread x-source byte offsets for both parities ----
    // q != cta : stripe q of x buffer b           -> b*PB + q*EF*4
    // q == cta : local staging buffer (b^1)       -> STG_OFF + cta*16 + (b^1)*256
    uint32_t off0, off1;
    if (q != cta) {
        off0 = (uint32_t)(q * (EF * 4));
        off1 = off0 + (uint32_t)PB;
    } else {
        off0 = (uint32_t)(STG_OFF + cta * 16 + 256);
        off1 = (uint32_t)(STG_OFF + cta * 16);
    }

    // peer smem bases for the 7 copy threads (dest skips self)
    uint32_t remB = 0;
    int dest = 0;
    if (tid < 7) {
        dest = tid + (tid >= cta ? 1 : 0);
        asm("mapa.shared::cluster.u32 %0, %1, %2;" : "=r"(remB) : "r"(sb), "r"(dest));
    }

    __syncthreads();
    asm volatile("barrier.cluster.arrive.aligned;" ::: "memory");
    asm volatile("barrier.cluster.wait.aligned;"   ::: "memory");

    // noise pipeline (epilogue threads), 2 deep; pair shares the address
    float vc = 0.0f, vn = 0.0f;
    if (epi) {
        vc = __ldg(vofT + cta * 64 + row);
        vn = __ldg(vofT + NREG + cta * 64 + row);
    }
    float2* outv = (float2*)out;

    // branchless epilogue constants by pair side
    const float Ha = par ? 615.0f : 310.0f;
    const float Hb = par ? 177.0f : 125.0f;
    const float Hd = par ? 0.087f : 0.16f;
    const float Hc = par ? 1e5f   : 1e9f;

    int ph0 = 0, ph1 = 0;

    for (int t = 0; t < NSTEPS; ++t) {
        const int b = t & 1;

        // ---- wait for this step's x data (skip t=0: local init) ----
        if (t) {
            const uint32_t mb = b ? mb1 : mb0;
            mbar_wait(mb, (uint32_t)(b ? ph1 : ph0));
            if (b) ph1 ^= 1; else ph0 ^= 1;
            if (tid == 0)
                asm volatile("mbarrier.arrive.expect_tx.shared.b64 _, [%0], %1;"
                             :: "r"(mb), "r"(1792) : "memory");
        }

        // ---- matvec: 64 cols/thread -> partial sum, STS ----
        const ulonglong2* x2 = (const ulonglong2*)
            ((const char*)smx + (b ? off1 : off0));
        unsigned long long a0 = 0ULL, a1 = 0ULL, a2 = 0ULL, a3 = 0ULL;
        #pragma unroll
        for (int it = 0; it < 8; ++it) {
            ulonglong2 xa = x2[2*it];
            ulonglong2 xb = x2[2*it+1];
            a0 = ffma2(c64[4*it+0], xa.x, a0);
            a1 = ffma2(c64[4*it+1], xa.y, a1);
            a2 = ffma2(c64[4*it+2], xb.x, a2);
            a3 = ffma2(c64[4*it+3], xb.y, a3);
        }
        smx[SUM_OFF / 4 + tid] =
            (fsum2(a0) + fsum2(a1)) + (fsum2(a2) + fsum2(a3));

        __syncthreads();   // partials visible; warps 4-15 sprint to next wait

        if (epi) {
            // ---- reduce 8 partials for my row (pair reads same addrs) ----
            const float4* sp = (const float4*)(smx + SUM_OFF / 4 + row * 8);
            float4 s0 = sp[0], s1 = sp[1];
            float acc = ((s0.x + s0.y) + (s0.z + s0.w))
                      + ((s1.x + s1.y) + (s1.z + s1.w));

            // ---- split epilogue: even lane H_E, odd lane H_I ----
            float I_E = 0.382f  + 0.21f * sE + 3.0f * acc - sI;  // LAMBDA=0
            float I_I = 0.2674f + 0.15f * sE - sI;
            float Iin = par ? I_I : I_E;
            float rMine  = Hfun(Iin, Ha, Hb, Hd, Hc);
            float rOther = __shfl_xor_sync(0xffffffffu, rMine, 1);
            float rE = par ? rOther : rMine;
            float rI = par ? rMine  : rOther;

            float dE = -sE * 0.01f + (1.0f - sE) * 6.41e-4f * rE + 0.01f * vc;
            float dI = -sI * 0.1f  + 1.0e-3f * rI + 0.01f * vc;
            sE = fmaf(1e-4f, dE, sE);
            sI = fmaf(1e-4f, dI, sI);

            // stage new S_E (even lanes), then copies ASAP
            if (par == 0)
                smx[(STG_OFF + cta * 16) / 4 + b * 64 + row] = sE;

            asm volatile("bar.sync 1, 128;" ::: "memory");  // staging ready

            if (tid < 7 && (t + 1 < NSTEPS)) {
                asm volatile("fence.proxy.async.shared::cta;" ::: "memory");
                uint32_t src = sb + (uint32_t)(STG_OFF + cta * 16 + b * 256);
                uint32_t dst = remB + (uint32_t)((b ? 0 : PB) + cta * (EF * 4));
                uint32_t rmb = remB + (uint32_t)(MB_OFF + ((b ^ 1) ? 8 : 0));
                asm volatile(
                    "cp.async.bulk.shared::cluster.shared::cta.mbarrier::complete_tx::bytes "
                    "[%0], [%1], %2, [%3];"
                    :: "r"(dst), "r"(src), "r"(256), "r"(rmb) : "memory");
            }

            // off critical path now: history + next noise
            if (par == 0)
                outv[512 + (size_t)t * NREG + cta * 64 + row] = make_float2(sE, sI);
            vc = vn;
            int t2 = t + 2; if (t2 >= NSTEPS) t2 = NSTEPS - 1;
            vn = __ldg(vofT + (size_t)t2 * NREG + cta * 64 + row);
        }
    }

    if (epi && par == 0) outv[cta * 64 + row] = make_float2(sE, sI);

    // drain: nobody exits while peers may still write our smem
    asm volatile("barrier.cluster.arrive.aligned;" ::: "memory");
    asm volatile("barrier.cluster.wait.aligned;"   ::: "memory");
}

extern "C" void kernel_launch(void* const* d_in, const int* in_sizes, int n_in,
                              void* d_out, int out_size) {
    const float* init = nullptr;
    const float* con  = nullptr;
    const float* v    = nullptr;
    for (int i = 0; i < n_in; ++i) {
        if      (in_sizes[i] == NREG * 2)      init = (const float*)d_in[i];
        else if (in_sizes[i] == NREG * NREG)   con  = (const float*)d_in[i];
        else if (in_sizes[i] == NSTEPS * NREG) v    = (const float*)d_in[i];
    }
    rww_kernel<<<NCTAS, NTHR, SMEM_BYTES>>>(init, con, v, (float*)d_out);
    (void)out_size;
}

// round 12
// speedup vs baseline: 1.4796x; 1.0008x over previous
#include <cuda_runtime.h>
#include <cstdint>
#include <cstddef>

// RWW whole-brain sim, 8-CTA cluster, Con_Mtx register-resident.
// R12 = R11 exchange (7x256B bulk copies + tx-mbarrier, champion) with the
//       epilogue hoisted into the wait window:
//   - I_I has NO network term (LAMBDA=0): the full H_I chain, the sI update,
//     and the affine coefficients of the sE update are computed BEFORE the
//     mbarrier wait (in the shadow of copy flight).
//   - post-acc chain is only: fmaf -> neg -> __expf -> denom -> div -> fmaf
//   - 64 epilogue threads, no pair-shfl needed.

#define NREG    512
#define NSTEPS  20000
#define NCTAS   8
#define NTHR    512

#define EF 68                          // x stripe stride floats (272 B)
#define PF 544                         // floats per x parity buffer
#define PB (PF * 4)                    // 2176 B
#define SUM_OFF  4352                  // 512 partial sums (2048 B)
#define STG_OFF  6400                  // staging: + cta*16 + b*256
#define MB_OFF   7424                  // 2 mbarriers
#define SMEM_BYTES 7680

__device__ __forceinline__ unsigned long long ffma2(
    unsigned long long a, unsigned long long b, unsigned long long c) {
    unsigned long long d;
    asm("fma.rn.f32x2 %0, %1, %2, %3;" : "=l"(d) : "l"(a), "l"(b), "l"(c));
    return d;
}
__device__ __forceinline__ float fsum2(unsigned long long a) {
    float2 f = *reinterpret_cast<float2*>(&a);
    return f.x + f.y;
}
__device__ __forceinline__ void mbar_wait(uint32_t mb, uint32_t par) {
    asm volatile(
        "{\n\t"
        ".reg .pred P;\n"
        "WL_%=:\n\t"
        "mbarrier.try_wait.parity.acquire.cluster.shared::cta.b64 P, [%0], %1, 0x989680;\n\t"
        "@!P bra WL_%=;\n\t"
        "}" :: "r"(mb), "r"(par) : "memory");
}

__device__ __forceinline__ float Hfun(float I, float a, float b, float d, float bigc) {
    float x     = fmaf(a, I, -b);
    float numer = fabsf(x) + 1e-9f;
    float neg   = -d * x;
    float e     = __expf(fminf(neg, 51.0f));
    float den_s = fabsf(1.0f - e) + 1e-9f * d;
    float den_b = fabsf(1.0f - bigc * neg) + 1e-9f * d;
    float denom = (neg > 50.0f) ? den_b : den_s;
    return __fdividef(numer, denom);
}

extern __shared__ float smx[];

__global__ void __launch_bounds__(NTHR, 1) __cluster_dims__(NCTAS, 1, 1)
rww_kernel(const float* __restrict__ init_state,   // (512, 2)
           const float* __restrict__ Con,          // (512, 512) row-major
           const float* __restrict__ vofT,         // (20000, 512)
           float* __restrict__ out)                // 1024 final + 20000*1024 hist
{
    const int tid  = (int)threadIdx.x;
    const int cta  = (int)blockIdx.x;          // cluster rank
    const int r    = tid >> 3;                 // local row 0..63
    const int q    = tid & 7;                  // column eighth 0..7
    const int j    = cta * 64 + r;             // global region of this row

    uint32_t sb;
    asm("{ .reg .u64 t; cvta.to.shared.u64 t, %1; cvt.u32.u64 %0, t; }"
        : "=r"(sb) : "l"(smx));
    const uint32_t mb0 = sb + MB_OFF;
    const uint32_t mb1 = sb + MB_OFF + 8;

    if (tid == 0) {
        asm volatile("mbarrier.init.shared.b64 [%0], %1;" :: "r"(mb0), "r"(1));
        asm volatile("mbarrier.init.shared.b64 [%0], %1;" :: "r"(mb1), "r"(1));
        asm volatile("mbarrier.arrive.expect_tx.shared.b64 _, [%0], %1;"
                     :: "r"(mb0), "r"(1792) : "memory");
        asm volatile("mbarrier.arrive.expect_tx.shared.b64 _, [%0], %1;"
                     :: "r"(mb1), "r"(1792) : "memory");
    }

    // ---- Con row segment: cols q*64..q*64+63 -> 32 packed f32x2 regs ----
    unsigned long long c64[32];
    {
        const ulonglong2* src =
            (const ulonglong2*)(Con + (size_t)j * NREG + (size_t)q * 64);
        #pragma unroll
        for (int it = 0; it < 16; ++it) {
            ulonglong2 t2 = src[it];
            c64[2*it] = t2.x; c64[2*it+1] = t2.y;
        }
    }

    // ---- init x buffer 0 locally: x[k] @ (k>>6)*EF + (k&63) ----
    if (tid < NREG)
        smx[(tid >> 6) * EF + (tid & 63)] = init_state[2 * tid];

    // ---- per-row state on threads 0..63 (row = tid) ----
    const bool epi = (tid < 64);
    float sE = 0.0f, sI = 0.0f;
    if (epi) {
        sE = init_state[2 * (cta * 64 + tid)];
        sI = init_state[2 * (cta * 64 + tid) + 1];
        // bootstrap staging buffer b'=1 (read at t=0 by q==cta threads)
        smx[(STG_OFF + cta * 16 + 256) / 4 + tid] = sE;
    }

    // ---- per-thread x-source byte offsets for both parities ----
    uint32_t off0, off1;
    if (q != cta) {
        off0 = (uint32_t)(q * (EF * 4));
        off1 = off0 + (uint32_t)PB;
    } else {
        off0 = (uint32_t)(STG_OFF + cta * 16 + 256);
        off1 = (uint32_t)(STG_OFF + cta * 16);
    }

    // peer smem bases for the 7 copy threads (dest skips self)
    uint32_t remB = 0;
    if (tid < 7) {
        int dest = tid + (tid >= cta ? 1 : 0);
        asm("mapa.shared::cluster.u32 %0, %1, %2;" : "=r"(remB) : "r"(sb), "r"(dest));
    }

    __syncthreads();
    asm volatile("barrier.cluster.arrive.aligned;" ::: "memory");
    asm volatile("barrier.cluster.wait.aligned;"   ::: "memory");

    // noise pipeline (epilogue threads), 2 deep
    float vc = 0.0f, vn = 0.0f;
    if (epi) {
        vc = __ldg(vofT + cta * 64 + tid);
        vn = __ldg(vofT + NREG + cta * 64 + tid);
    }
    float2* outv = (float2*)out;

    int ph0 = 0, ph1 = 0;

    for (int t = 0; t < NSTEPS; ++t) {
        const int b = t & 1;

        // ---- PRECOMPUTE in the flight window (state t fully known) ----
        // I_I has no network term (LAMBDA=0): full H_I + sI update here.
        float xE0 = 0.0f, BE = 0.0f, CE = 0.0f, sI_next = 0.0f;
        if (epi) {
            float I_E0 = 0.382f + 0.21f * sE - sI;           // I_E minus 3*acc
            xE0 = fmaf(310.0f, I_E0, -125.0f);
            float I_I  = 0.2674f + 0.15f * sE - sI;
            float rI   = Hfun(I_I, 615.0f, 177.0f, 0.087f, 1e5f);
            BE = 6.41e-8f * (1.0f - sE);                      // dt*gamma*(1-sE)
            CE = fmaf(1e-4f, fmaf(0.01f, vc, -0.01f * sE), sE);
            sI_next = fmaf(1e-7f, rI,
                           fmaf(1e-4f, fmaf(0.01f, vc, -0.1f * sI), sI));
        }

        // ---- wait for this step's x data (skip t=0: local init) ----
        if (t) {
            const uint32_t mb = b ? mb1 : mb0;
            mbar_wait(mb, (uint32_t)(b ? ph1 : ph0));
            if (b) ph1 ^= 1; else ph0 ^= 1;
            if (tid == 0)
                asm volatile("mbarrier.arrive.expect_tx.shared.b64 _, [%0], %1;"
                             :: "r"(mb), "r"(1792) : "memory");
        }

        // ---- matvec: 64 cols/thread -> partial sum, STS ----
        const ulonglong2* x2 = (const ulonglong2*)
            ((const char*)smx + (b ? off1 : off0));
        unsigned long long a0 = 0ULL, a1 = 0ULL, a2 = 0ULL, a3 = 0ULL;
        #pragma unroll
        for (int it = 0; it < 8; ++it) {
            ulonglong2 xa = x2[2*it];
            ulonglong2 xb = x2[2*it+1];
            a0 = ffma2(c64[4*it+0], xa.x, a0);
            a1 = ffma2(c64[4*it+1], xa.y, a1);
            a2 = ffma2(c64[4*it+2], xb.x, a2);
            a3 = ffma2(c64[4*it+3], xb.y, a3);
        }
        smx[SUM_OFF / 4 + tid] =
            (fsum2(a0) + fsum2(a1)) + (fsum2(a2) + fsum2(a3));

        __syncthreads();   // partials visible; warps 2-15 sprint to next wait

        if (epi) {
            // ---- reduce 8 partials for my row ----
            const float4* sp = (const float4*)(smx + SUM_OFF / 4 + tid * 8);
            float4 s0 = sp[0], s1 = sp[1];
            float acc = ((s0.x + s0.y) + (s0.z + s0.w))
                      + ((s1.x + s1.y) + (s1.z + s1.w));

            // ---- minimal post-acc chain: H_E only ----
            float xE   = fmaf(930.0f, acc, xE0);              // 310*(I_E)-125
            float negE = -0.16f * xE;
            float e    = __expf(fminf(negE, 51.0f));
            float den  = (negE > 50.0f)
                       ? (fabsf(fmaf(-1e9f, negE, 1.0f)) + 1.6e-10f)
                       : (fabsf(1.0f - e) + 1.6e-10f);
            float rE   = __fdividef(fabsf(xE) + 1e-9f, den);
            sE = fmaf(BE, rE, CE);
            sI = sI_next;

            // stage new S_E, then copies ASAP
            smx[(STG_OFF + cta * 16) / 4 + b * 64 + tid] = sE;

            asm volatile("bar.sync 1, 64;" ::: "memory");     // staging ready

            if (tid < 7 && (t + 1 < NSTEPS)) {
                asm volatile("fence.proxy.async.shared::cta;" ::: "memory");
                uint32_t src = sb + (uint32_t)(STG_OFF + cta * 16 + b * 256);
                uint32_t dst = remB + (uint32_t)((b ? 0 : PB) + cta * (EF * 4));
                uint32_t rmb = remB + (uint32_t)(MB_OFF + ((b ^ 1) ? 8 : 0));
                asm volatile(
                    "cp.async.bulk.shared::cluster.shared::cta.mbarrier::complete_tx::bytes "
                    "[%0], [%1], %2, [%3];"
                    :: "r"(dst), "r"(src), "r"(256), "r"(rmb) : "memory");
            }

            // off critical path: history + next noise
            outv[512 + (size_t)t * NREG + cta * 64 + tid] = make_float2(sE, sI);
            vc = vn;
            int t2 = t + 2; if (t2 >= NSTEPS) t2 = NSTEPS - 1;
            vn = __ldg(vofT + (size_t)t2 * NREG + cta * 64 + tid);
        }
    }

    if (epi) outv[cta * 64 + tid] = make_float2(sE, sI);

    // drain: nobody exits while peers may still write our smem
    asm volatile("barrier.cluster.arrive.aligned;" ::: "memory");
    asm volatile("barrier.cluster.wait.aligned;"   ::: "memory");
}

extern "C" void kernel_launch(void* const* d_in, const int* in_sizes, int n_in,
                              void* d_out, int out_size) {
    const float* init = nullptr;
    const float* con  = nullptr;
    const float* v    = nullptr;
    for (int i = 0; i < n_in; ++i) {
        if      (in_sizes[i] == NREG * 2)      init = (const float*)d_in[i];
        else if (in_sizes[i] == NREG * NREG)   con  = (const float*)d_in[i];
        else if (in_sizes[i] == NSTEPS * NREG) v    = (const float*)d_in[i];
    }
    rww_kernel<<<NCTAS, NTHR, SMEM_BYTES>>>(init, con, v, (float*)d_out);
    (void)out_size;
}

// round 13
// speedup vs baseline: 1.9945x; 1.3480x over previous
#include <cuda_runtime.h>
#include <cstdint>
#include <cstddef>

// RWW whole-brain sim, 8-CTA cluster, Con_Mtx register-resident.
// R13: per-stripe warp-uniform waits.
//   - warp w owns stripe q=w&7 (rows (w>>3)*32+lane, cols q*64..+63); it
//     waits ONLY on mbarrier[b][q] (uniform in-warp -> no divergence).
//     Early stripes are multiplied while late copies are still in flight;
//     post-last-arrival matvec shrinks from ~250 cyc (full CTA) to ~80.
//   - x loads are warp-broadcast (all lanes same address): no padding.
//   - exchange unchanged from champion: 7x256B bulk copies + tx mbarriers.
//   - self stripe reads local staging, gated by a local mbarrier LB[buf]
//     (remote copies don't transitively order MY epilogue -> real race).
//   - sums double-buffered (fast warp's t+1 STS vs epilogue's t read race).
//   - epilogue on warps 14-15 (hi-wid arbiter priority).
//   - arithmetic EXACTLY R11 (restores rel_err ~3.2e-8); only the
//     bit-identical rI chain is hoisted before the wait.

#define NREG    512
#define NSTEPS  20000
#define NCTAS   8
#define NTHR    512

// smem byte map
#define X_OFF    0        // x[2][512] floats          (4096 B)
#define SUM_OFF  4096     // sums[2][512] floats       (4096 B)
#define STG_OFF  8192     // staging[2][64] floats     (512 B)
#define MB_OFF   8704     // 16 src mbarriers          (128 B)
#define LB_OFF   8832     // 2 local mbarriers         (16 B)
#define SMEM_BYTES 8960

__device__ __forceinline__ unsigned long long ffma2(
    unsigned long long a, unsigned long long b, unsigned long long c) {
    unsigned long long d;
    asm("fma.rn.f32x2 %0, %1, %2, %3;" : "=l"(d) : "l"(a), "l"(b), "l"(c));
    return d;
}
__device__ __forceinline__ float fsum2(unsigned long long a) {
    float2 f = *reinterpret_cast<float2*>(&a);
    return f.x + f.y;
}
__device__ __forceinline__ void mbar_wait(uint32_t mb, uint32_t par) {
    asm volatile(
        "{\n\t"
        ".reg .pred P;\n"
        "WL_%=:\n\t"
        "mbarrier.try_wait.parity.acquire.cluster.shared::cta.b64 P, [%0], %1, 0x989680;\n\t"
        "@!P bra WL_%=;\n\t"
        "}" :: "r"(mb), "r"(par) : "memory");
}

__device__ __forceinline__ float Hfun(float I, float a, float b, float d, float bigc) {
    float x     = fmaf(a, I, -b);
    float numer = fabsf(x) + 1e-9f;
    float neg   = -d * x;
    float e     = __expf(fminf(neg, 51.0f));
    float den_s = fabsf(1.0f - e) + 1e-9f * d;
    float den_b = fabsf(1.0f - bigc * neg) + 1e-9f * d;
    float denom = (neg > 50.0f) ? den_b : den_s;
    return __fdividef(numer, denom);
}

extern __shared__ float smx[];

__global__ void __launch_bounds__(NTHR, 1) __cluster_dims__(NCTAS, 1, 1)
rww_kernel(const float* __restrict__ init_state,   // (512, 2)
           const float* __restrict__ Con,          // (512, 512) row-major
           const float* __restrict__ vofT,         // (20000, 512)
           float* __restrict__ out)                // 1024 final + 20000*1024 hist
{
    const int tid  = (int)threadIdx.x;
    const int cta  = (int)blockIdx.x;          // cluster rank
    const int lane = tid & 31;
    const int w    = tid >> 5;                 // warp 0..15
    const int q    = w & 7;                    // stripe (source CTA) of warp
    const int rmv  = ((w >> 3) << 5) + lane;   // matvec row 0..63
    const bool isLocal = (q == cta);

    const bool epi  = (tid >= 448);            // warps 14-15: epilogue
    const int  erow = tid - 448;               // epilogue row 0..63

    uint32_t sb;
    asm("{ .reg .u64 t; cvta.to.shared.u64 t, %1; cvt.u32.u64 %0, t; }"
        : "=r"(sb) : "l"(smx));

    // ---- 16 src mbarriers [buf][src]: count=1, phase-0 tx armed ----
    if (tid < 16) {
        uint32_t mb = sb + MB_OFF + (uint32_t)(tid * 8);
        asm volatile("mbarrier.init.shared.b64 [%0], %1;" :: "r"(mb), "r"(1));
        asm volatile("mbarrier.arrive.expect_tx.shared.b64 _, [%0], %1;"
                     :: "r"(mb), "r"(256) : "memory");
    }
    // ---- 2 local mbarriers (staging guards), count=1 ----
    if (tid == 16) {
        asm volatile("mbarrier.init.shared.b64 [%0], %1;" :: "r"(sb + LB_OFF), "r"(1));
        asm volatile("mbarrier.init.shared.b64 [%0], %1;" :: "r"(sb + LB_OFF + 8), "r"(1));
    }

    // ---- Con: row cta*64+rmv, cols q*64..q*64+63 -> 32 f32x2 regs ----
    unsigned long long c64[32];
    {
        const ulonglong2* src = (const ulonglong2*)
            (Con + (size_t)(cta * 64 + rmv) * NREG + (size_t)q * 64);
        #pragma unroll
        for (int it = 0; it < 16; ++it) {
            ulonglong2 t2 = src[it];
            c64[2*it] = t2.x; c64[2*it+1] = t2.y;
        }
    }

    // ---- init x buffer 0 (contiguous; warp reads are broadcast) ----
    smx[tid < NREG ? tid : 0] = smx[0];   // no-op guard shape
    if (tid < NREG) smx[tid] = init_state[2 * tid];

    // ---- epilogue state (row = erow) + staging[1] bootstrap ----
    float sE = 0.0f, sI = 0.0f;
    if (epi) {
        sE = init_state[2 * (cta * 64 + erow)];
        sI = init_state[2 * (cta * 64 + erow) + 1];
        smx[(STG_OFF + 256) / 4 + erow] = sE;   // staging[1] for t=0 self-read
    }

    // ---- copy threads (tid 448..454): peer smem bases ----
    uint32_t remB = 0;
    if (tid >= 448 && tid < 455) {
        int d = tid - 448;
        int dest = d + (d >= cta ? 1 : 0);
        asm("mapa.shared::cluster.u32 %0, %1, %2;" : "=r"(remB) : "r"(sb), "r"(dest));
    }

    __syncthreads();
    asm volatile("barrier.cluster.arrive.aligned;" ::: "memory");
    asm volatile("barrier.cluster.wait.aligned;"   ::: "memory");

    float vc = 0.0f, vn = 0.0f;
    if (epi) {
        vc = __ldg(vofT + cta * 64 + erow);
        vn = __ldg(vofT + NREG + cta * 64 + erow);
    }
    float2* outv = (float2*)out;

    int pb0 = 0, pb1 = 0;     // parities: src barrier per buf (non-local warps)
    int pl0 = 0, pl1 = 0;     // parities: local barrier per buf (local warps)

    for (int t = 0; t < NSTEPS; ++t) {
        const int b = t & 1;

        // ---- hoisted, bit-identical rI chain (no network term) ----
        float rI = 0.0f;
        if (epi) {
            float I_I = 0.2674f + 0.15f * sE - sI;
            rI = Hfun(I_I, 615.0f, 177.0f, 0.087f, 1e5f);
        }

        // ---- per-warp wait (uniform in-warp) ----
        if (t) {
            if (!isLocal) {
                uint32_t mb = sb + MB_OFF + (uint32_t)((b * 8 + q) * 8);
                if (b) { mbar_wait(mb, (uint32_t)pb1); pb1 ^= 1; }
                else   { mbar_wait(mb, (uint32_t)pb0); pb0 ^= 1; }
                if (lane == 0 && w < 8)   // one re-arm per barrier
                    asm volatile("mbarrier.arrive.expect_tx.shared.b64 _, [%0], %1;"
                                 :: "r"(mb), "r"(256) : "memory");
            } else {
                uint32_t lb = sb + LB_OFF + (uint32_t)((b ^ 1) * 8);
                if (b ^ 1) { mbar_wait(lb, (uint32_t)pl1); pl1 ^= 1; }
                else       { mbar_wait(lb, (uint32_t)pl0); pl0 ^= 1; }
            }
        }

        // ---- matvec: 64 cols of stripe q (broadcast LDS), row rmv ----
        const ulonglong2* x2 = isLocal
            ? (const ulonglong2*)((const char*)smx + STG_OFF + (b ^ 1) * 256)
            : (const ulonglong2*)((const char*)smx + X_OFF + b * 2048 + q * 256);
        unsigned long long a0 = 0ULL, a1 = 0ULL, a2 = 0ULL, a3 = 0ULL;
        #pragma unroll
        for (int it = 0; it < 8; ++it) {
            ulonglong2 xa = x2[2*it];
            ulonglong2 xb = x2[2*it+1];
            a0 = ffma2(c64[4*it+0], xa.x, a0);
            a1 = ffma2(c64[4*it+1], xa.y, a1);
            a2 = ffma2(c64[4*it+2], xb.x, a2);
            a3 = ffma2(c64[4*it+3], xb.y, a3);
        }
        // partial for (row rmv, stripe q) -> sums[b][q*64 + rmv]
        smx[(SUM_OFF + b * 2048) / 4 + q * 64 + rmv] =
            (fsum2(a0) + fsum2(a1)) + (fsum2(a2) + fsum2(a3));

        __syncthreads();   // all stripes' partials visible

        if (epi) {
            // ---- reduce 8 partials for my row (same tree as R11) ----
            const float* su = smx + (SUM_OFF + b * 2048) / 4 + erow;
            float p0 = su[0*64], p1 = su[1*64], p2 = su[2*64], p3 = su[3*64];
            float p4 = su[4*64], p5 = su[5*64], p6 = su[6*64], p7 = su[7*64];
            float acc = ((p0 + p1) + (p2 + p3)) + ((p4 + p5) + (p6 + p7));

            // ---- epilogue: EXACT R11 expressions ----
            float I_E = 0.382f  + 0.21f * sE + 3.0f * acc - sI;  // LAMBDA=0
            float rE = Hfun(I_E, 310.0f, 125.0f, 0.16f,  1e9f);
            float dE = -sE * 0.01f + (1.0f - sE) * 6.41e-4f * rE + 0.01f * vc;
            float dI = -sI * 0.1f  + 1.0e-3f * rI + 0.01f * vc;
            sE = fmaf(1e-4f, dE, sE);
            sI = fmaf(1e-4f, dI, sI);

            // stage new S_E
            smx[(STG_OFF + b * 256) / 4 + erow] = sE;

            asm volatile("bar.sync 1, 64;" ::: "memory");   // warps 14-15

            // unblock local-stripe warps ASAP (release; consumers acquire)
            if (tid == 448)
                asm volatile("mbarrier.arrive.shared.b64 _, [%0];"
                             :: "r"(sb + LB_OFF + (uint32_t)(b * 8)) : "memory");

            // ---- 7 parallel 256B bulk copies (data + tx fused) ----
            if (tid < 455 && (t + 1 < NSTEPS)) {
                asm volatile("fence.proxy.async.shared::cta;" ::: "memory");
                uint32_t src = sb + (uint32_t)(STG_OFF + b * 256);
                uint32_t dst = remB + (uint32_t)(X_OFF + (b ^ 1) * 2048 + cta * 256);
                uint32_t rmb = remB + (uint32_t)(MB_OFF + (((b ^ 1) * 8) + cta) * 8);
                asm volatile(
                    "cp.async.bulk.shared::cluster.shared::cta.mbarrier::complete_tx::bytes "
                    "[%0], [%1], %2, [%3];"
                    :: "r"(dst), "r"(src), "r"(256), "r"(rmb) : "memory");
            }

            // off critical path: history + next noise
            outv[512 + (size_t)t * NREG + cta * 64 + erow] = make_float2(sE, sI);
            vc = vn;
            int t2 = t + 2; if (t2 >= NSTEPS) t2 = NSTEPS - 1;
            vn = __ldg(vofT + (size_t)t2 * NREG + cta * 64 + erow);
        }
    }

    if (epi) outv[cta * 64 + erow] = make_float2(sE, sI);

    // drain: nobody exits while peers may still write our smem
    asm volatile("barrier.cluster.arrive.aligned;" ::: "memory");
    asm volatile("barrier.cluster.wait.aligned;"   ::: "memory");
}

extern "C" void kernel_launch(void* const* d_in, const int* in_sizes, int n_in,
                              void* d_out, int out_size) {
    const float* init = nullptr;
    const float* con  = nullptr;
    const float* v    = nullptr;
    for (int i = 0; i < n_in; ++i) {
        if      (in_sizes[i] == NREG * 2)      init = (const float*)d_in[i];
        else if (in_sizes[i] == NREG * NREG)   con  = (const float*)d_in[i];
        else if (in_sizes[i] == NSTEPS * NREG) v    = (const float*)d_in[i];
    }
    rww_kernel<<<NCTAS, NTHR, SMEM_BYTES>>>(init, con, v, (float*)d_out);
    (void)out_size;
}